// round 9
// baseline (speedup 1.0000x reference)
#include <cuda_runtime.h>
#include <math.h>

#define GRID 592          // 4 blocks/SM x 148 SMs -> co-resident on 148- and 152-SM parts
#define CK 16             // k-split for gram: 2*16*CK = 512 gram blocks
#define SMEM_BYTES 49152  // 48 KB dynamic: 3 stages x 4 warps x 4 KB

// ---------------- scratch (device globals; no allocations) ----------------
__device__ float g_means[2][2][256][1024]; // [half][tensor][class][d] partial sums
__device__ float g_gram[CK][2][256][256];  // partial grams
__device__ float g_rowloss[256];
__device__ int   g_bar1, g_bar2, g_done;   // barrier counters (self-resetting)

__device__ __forceinline__ void grid_barrier(int* ctr) {
    __syncthreads();
    if (threadIdx.x == 0) {
        __threadfence();
        atomicAdd(ctr, 1);
        while (*((volatile int*)ctr) < GRID) __nanosleep(64);
    }
    __syncthreads();
}

extern __shared__ __align__(16) unsigned char s_raw[];

__global__ void __launch_bounds__(128, 4)
fused_kernel(const float* __restrict__ emb, const float* __restrict__ feat,
             float* __restrict__ out) {
    __shared__ float s_red[4];
    __shared__ int   s_last;

    int tid = threadIdx.x, lane = tid & 31, w = tid >> 5;

    // ================= phase 1: fused normalize + class mean =================
    // 1024 half-class units grid-strided over 592 blocks (fine granularity ->
    // <=2% imbalance). Block = 4 warps; warp w owns 8 samples of its half;
    // lane owns float4 chunks j*32+lane. 3-stage cp.async, 8 KB/warp in flight.
    {
        float4* sm4 = (float4*)s_raw;   // [(stage*4 + warp)*256 + pos]

        for (int u = blockIdx.x; u < 1024; u += GRID) {
            int c = u & 255;
            int t = (u >> 8) & 1;
            int h = u >> 9;             // half: samples [h*32, h*32+32)
            const float4* base4 = (const float4*)((t == 0 ? emb : feat)
                                   + (size_t)c * 65536)
                                   + (size_t)(h * 32 + w * 8) * 256;

            float4 acc[8];
            #pragma unroll
            for (int j = 0; j < 8; j++) acc[j] = make_float4(0.f, 0.f, 0.f, 0.f);

            #define ISSUE(n, st) do {                                                 \
                unsigned _d = (unsigned)__cvta_generic_to_shared(                     \
                                  &sm4[((st) * 4 + w) * 256 + lane]);                 \
                const float4* _s = base4 + (size_t)(n) * 256 + lane;                  \
                _Pragma("unroll")                                                     \
                for (int j = 0; j < 8; j++)                                           \
                    asm volatile("cp.async.cg.shared.global [%0], [%1], 16;"          \
                                 :: "r"(_d + j * 512), "l"(_s + j * 32));             \
                asm volatile("cp.async.commit_group;");                               \
            } while (0)

            ISSUE(0, 0); ISSUE(1, 1); ISSUE(2, 2);

            #pragma unroll 1
            for (int n = 0; n < 8; n++) {
                asm volatile("cp.async.wait_group 2;" ::: "memory");
                int st = n % 3;
                const float4* sb = &sm4[(st * 4 + w) * 256];

                float4 v[8];
                #pragma unroll
                for (int j = 0; j < 8; j++) v[j] = sb[j * 32 + lane];

                // free the stage immediately for the next prefetch
                if (n + 3 < 8) { ISSUE(n + 3, st); }
                else { asm volatile("cp.async.commit_group;"); }

                // 4-way split sum-of-squares (short dependency chains)
                float s0 = v[0].x * v[0].x + v[0].y * v[0].y + v[0].z * v[0].z + v[0].w * v[0].w;
                float s1 = v[1].x * v[1].x + v[1].y * v[1].y + v[1].z * v[1].z + v[1].w * v[1].w;
                float s2 = v[2].x * v[2].x + v[2].y * v[2].y + v[2].z * v[2].z + v[2].w * v[2].w;
                float s3 = v[3].x * v[3].x + v[3].y * v[3].y + v[3].z * v[3].z + v[3].w * v[3].w;
                s0 += v[4].x * v[4].x + v[4].y * v[4].y + v[4].z * v[4].z + v[4].w * v[4].w;
                s1 += v[5].x * v[5].x + v[5].y * v[5].y + v[5].z * v[5].z + v[5].w * v[5].w;
                s2 += v[6].x * v[6].x + v[6].y * v[6].y + v[6].z * v[6].z + v[6].w * v[6].w;
                s3 += v[7].x * v[7].x + v[7].y * v[7].y + v[7].z * v[7].z + v[7].w * v[7].w;
                float ss = (s0 + s1) + (s2 + s3);
                #pragma unroll
                for (int o = 16; o; o >>= 1) ss += __shfl_xor_sync(0xffffffffu, ss, o);
                float inv = 1.0f / fmaxf(sqrtf(ss), 1e-12f);

                #pragma unroll
                for (int j = 0; j < 8; j++) {
                    acc[j].x += v[j].x * inv;
                    acc[j].y += v[j].y * inv;
                    acc[j].z += v[j].z * inv;
                    acc[j].w += v[j].w * inv;
                }
            }
            #undef ISSUE

            // cross-warp combine in staging area (each warp drained its own groups)
            __syncthreads();
            #pragma unroll
            for (int j = 0; j < 8; j++) sm4[w * 256 + j * 32 + lane] = acc[j];
            __syncthreads();
            #pragma unroll
            for (int i2 = tid; i2 < 256; i2 += 128) {
                float4 r = sm4[i2];
                #pragma unroll
                for (int w2 = 1; w2 < 4; w2++) {
                    float4 vv = sm4[w2 * 256 + i2];
                    r.x += vv.x; r.y += vv.y; r.z += vv.z; r.w += vv.w;
                }
                ((float4*)&g_means[h][t][c][0])[i2] = r;  // SUM; /64 folded into gram
            }
            __syncthreads();  // protect staging before next unit's ISSUE
        }
    }

    grid_barrier(&g_bar1);

    // ================= phase 2: gram = means @ means^T =================
    // 512 active blocks: tensor(2) x tile(16: 4x4 of 64x64) x ks(CK=16, k=64).
    // 128 threads, 8x4 micro-tile, fma.rn.f32x2. Halves summed at smem fill.
    if (blockIdx.x < 512) {
        int b    = blockIdx.x;
        int ks   = b & 15;
        int it   = b >> 4;          // 0..31
        int t    = it >> 4;
        int tile = it & 15;
        int i0 = (tile >> 2) * 64, j0 = (tile & 3) * 64;
        const float* A0 = &g_means[0][t][0][0];
        const float* A1 = &g_means[1][t][0][0];

        float (*As)[68] = (float(*)[68])s_raw;             // 64x68 (17408 B)
        float (*Bs)[68] = (float(*)[68])(s_raw + 17408);

        int tx = tid & 15, ty = tid >> 4;   // 16 x 8
        unsigned long long acc[8][2];
        #pragma unroll
        for (int uu = 0; uu < 8; uu++) { acc[uu][0] = 0ull; acc[uu][1] = 0ull; }

        int kk = ks * 64;
        #pragma unroll
        for (int l = 0; l < 8; l++) {
            int idx = tid + l * 128;
            int r = idx >> 4, f4 = idx & 15;
            size_t oi = (size_t)(i0 + r) * 1024 + kk + f4 * 4;
            size_t oj = (size_t)(j0 + r) * 1024 + kk + f4 * 4;
            float4 va0 = *(const float4*)&A0[oi];
            float4 va1 = *(const float4*)&A1[oi];
            As[f4 * 4 + 0][r] = va0.x + va1.x;
            As[f4 * 4 + 1][r] = va0.y + va1.y;
            As[f4 * 4 + 2][r] = va0.z + va1.z;
            As[f4 * 4 + 3][r] = va0.w + va1.w;
            float4 vb0 = *(const float4*)&A0[oj];
            float4 vb1 = *(const float4*)&A1[oj];
            Bs[f4 * 4 + 0][r] = vb0.x + vb1.x;
            Bs[f4 * 4 + 1][r] = vb0.y + vb1.y;
            Bs[f4 * 4 + 2][r] = vb0.z + vb1.z;
            Bs[f4 * 4 + 3][r] = vb0.w + vb1.w;
        }
        __syncthreads();
        #pragma unroll 4
        for (int k = 0; k < 64; k++) {
            float4 a0 = *(const float4*)&As[k][ty * 8];
            float4 a1 = *(const float4*)&As[k][ty * 8 + 4];
            ulonglong2 bv = *(const ulonglong2*)&Bs[k][tx * 4];
            unsigned long long p0, p1, p2, p3, p4, p5, p6, p7;
            asm("mov.b64 %0,{%1,%1};" : "=l"(p0) : "f"(a0.x));
            asm("mov.b64 %0,{%1,%1};" : "=l"(p1) : "f"(a0.y));
            asm("mov.b64 %0,{%1,%1};" : "=l"(p2) : "f"(a0.z));
            asm("mov.b64 %0,{%1,%1};" : "=l"(p3) : "f"(a0.w));
            asm("mov.b64 %0,{%1,%1};" : "=l"(p4) : "f"(a1.x));
            asm("mov.b64 %0,{%1,%1};" : "=l"(p5) : "f"(a1.y));
            asm("mov.b64 %0,{%1,%1};" : "=l"(p6) : "f"(a1.z));
            asm("mov.b64 %0,{%1,%1};" : "=l"(p7) : "f"(a1.w));
            asm("fma.rn.f32x2 %0,%1,%2,%0;" : "+l"(acc[0][0]) : "l"(p0), "l"(bv.x));
            asm("fma.rn.f32x2 %0,%1,%2,%0;" : "+l"(acc[0][1]) : "l"(p0), "l"(bv.y));
            asm("fma.rn.f32x2 %0,%1,%2,%0;" : "+l"(acc[1][0]) : "l"(p1), "l"(bv.x));
            asm("fma.rn.f32x2 %0,%1,%2,%0;" : "+l"(acc[1][1]) : "l"(p1), "l"(bv.y));
            asm("fma.rn.f32x2 %0,%1,%2,%0;" : "+l"(acc[2][0]) : "l"(p2), "l"(bv.x));
            asm("fma.rn.f32x2 %0,%1,%2,%0;" : "+l"(acc[2][1]) : "l"(p2), "l"(bv.y));
            asm("fma.rn.f32x2 %0,%1,%2,%0;" : "+l"(acc[3][0]) : "l"(p3), "l"(bv.x));
            asm("fma.rn.f32x2 %0,%1,%2,%0;" : "+l"(acc[3][1]) : "l"(p3), "l"(bv.y));
            asm("fma.rn.f32x2 %0,%1,%2,%0;" : "+l"(acc[4][0]) : "l"(p4), "l"(bv.x));
            asm("fma.rn.f32x2 %0,%1,%2,%0;" : "+l"(acc[4][1]) : "l"(p4), "l"(bv.y));
            asm("fma.rn.f32x2 %0,%1,%2,%0;" : "+l"(acc[5][0]) : "l"(p5), "l"(bv.x));
            asm("fma.rn.f32x2 %0,%1,%2,%0;" : "+l"(acc[5][1]) : "l"(p5), "l"(bv.y));
            asm("fma.rn.f32x2 %0,%1,%2,%0;" : "+l"(acc[6][0]) : "l"(p6), "l"(bv.x));
            asm("fma.rn.f32x2 %0,%1,%2,%0;" : "+l"(acc[6][1]) : "l"(p6), "l"(bv.y));
            asm("fma.rn.f32x2 %0,%1,%2,%0;" : "+l"(acc[7][0]) : "l"(p7), "l"(bv.x));
            asm("fma.rn.f32x2 %0,%1,%2,%0;" : "+l"(acc[7][1]) : "l"(p7), "l"(bv.y));
        }
        const float scale = 1.0f / 4096.0f;   // (1/64)^2
        #pragma unroll
        for (int uu = 0; uu < 8; uu++) {
            #pragma unroll
            for (int vp = 0; vp < 2; vp++) {
                float lo, hi;
                asm("mov.b64 {%0,%1},%2;" : "=f"(lo), "=f"(hi) : "l"(acc[uu][vp]));
                int r  = i0 + ty * 8 + uu;
                int c0 = j0 + tx * 4 + 2 * vp;
                g_gram[ks][t][r][c0 + 0] = lo * scale;
                g_gram[ks][t][r][c0 + 1] = hi * scale;
            }
        }
    }

    grid_barrier(&g_bar2);

    // ================= phase 3: ListMLE per row + final mean =================
    if (blockIdx.x < 256) {
        int i = blockIdx.x;
        float* tr = (float*)s_raw;            // 256 floats
        float* ps = (float*)(s_raw + 1024);   // 256 floats

        float p0 = 0.f, t0 = 0.f, p1 = 0.f, t1 = 0.f;
        #pragma unroll
        for (int ks = 0; ks < CK; ks++) {
            p0 += g_gram[ks][0][i][tid];
            p1 += g_gram[ks][0][i][tid + 128];
            t0 += g_gram[ks][1][i][tid];
            t1 += g_gram[ks][1][i][tid + 128];
        }
        tr[tid] = t0; tr[tid + 128] = t1;
        __syncthreads();

        // stable descending rank (ties keep ascending index = argsort(-true))
        int r0 = 0, r1 = 0;
        #pragma unroll 8
        for (int k = 0; k < 256; k++) {
            float tk = tr[k];
            r0 += (tk > t0) || (tk == t0 && k < tid);
            r1 += (tk > t1) || (tk == t1 && k < tid + 128);
        }
        ps[r0] = p0;
        ps[r1] = p1;
        __syncthreads();

        // thread owns sorted positions (2*tid, 2*tid+1)
        float e0 = ps[2 * tid], e1 = ps[2 * tid + 1];
        float x0 = __expf(e0), x1 = __expf(e1);
        float s = x0 + x1;

        #pragma unroll
        for (int off = 1; off < 32; off <<= 1) {
            float v = __shfl_down_sync(0xffffffffu, s, off);
            if (lane + off < 32) s += v;
        }
        if (lane == 0) s_red[w] = s;
        __syncthreads();
        float tail = 0.f;
        #pragma unroll
        for (int w2 = 0; w2 < 4; w2++) if (w2 > w) tail += s_red[w2];
        float S = s + tail;                 // suffix sum at position 2*tid

        float term = (__logf(S + 1e-10f) - e0)
                   + (__logf(S - x0 + 1e-10f) - e1);
        __syncthreads();
        #pragma unroll
        for (int o = 16; o; o >>= 1) term += __shfl_xor_sync(0xffffffffu, term, o);
        if (lane == 0) s_red[w] = term;
        __syncthreads();
        if (tid == 0) {
            g_rowloss[i] = s_red[0] + s_red[1] + s_red[2] + s_red[3];
            __threadfence();
            int v = atomicAdd(&g_done, 1);
            s_last = (v == 255);
        }
        __syncthreads();

        if (s_last) {
            volatile float* rl = g_rowloss;
            float v = rl[tid] + rl[tid + 128];
            #pragma unroll
            for (int o = 16; o; o >>= 1) v += __shfl_xor_sync(0xffffffffu, v, o);
            if (lane == 0) s_red[w] = v;
            __syncthreads();
            if (tid == 0) {
                out[0] = (s_red[0] + s_red[1] + s_red[2] + s_red[3]) * (1.0f / 256.0f);
                g_done = 0;   // reset counters for next graph replay
                g_bar1 = 0;
                g_bar2 = 0;
            }
        }
    }
}

// ---------------- launch ----------------
extern "C" void kernel_launch(void* const* d_in, const int* in_sizes, int n_in,
                              void* d_out, int out_size) {
    const float* emb  = (const float*)d_in[0];
    const float* feat = (const float*)d_in[1];
    float* out = (float*)d_out;

    cudaFuncSetAttribute(fused_kernel,
                         cudaFuncAttributeMaxDynamicSharedMemorySize, SMEM_BYTES);
    fused_kernel<<<GRID, 128, SMEM_BYTES>>>(emb, feat, out);
}

// round 10
// speedup vs baseline: 1.0450x; 1.0450x over previous
#include <cuda_runtime.h>
#include <math.h>

#define CK 16   // k-split for gram: 2 tensors x 16 tiles x CK = 512 blocks
#define GRIDB 512

// ---------------- scratch (device globals; no allocations) ----------------
__device__ float g_means[2][2][256][1024]; // [half][tensor][class][d] partial sums
__device__ float g_gram[CK][2][256][256];  // partial grams
__device__ float g_rowloss[256];
__device__ int   g_bar1, g_done;           // barrier counters (self-resetting)

// ================= kernel A: fused normalize + class mean (R5 verbatim) =====
// grid 1024 = half(2) x tensor(2) x class(256); block 128 = 4 warps.
// Warp w handles 8 samples; lane owns float4 chunks j*32+lane of D=1024.
// 3-stage warp-private cp.async staging. Measured 25.0 us.
#define STAGES 3
__global__ void __launch_bounds__(128) means_kernel(const float* __restrict__ emb,
                                                    const float* __restrict__ feat) {
    __shared__ float4 s_buf[STAGES][4][256];   // 48 KB exactly

    int b = blockIdx.x;
    int c = b & 255;
    int t = (b >> 8) & 1;
    int h = b >> 9;                            // sample half: [h*32, h*32+32)
    const float4* xv = (const float4*)((t == 0 ? emb : feat) + (size_t)c * 64 * 1024);
    int tid = threadIdx.x, lane = tid & 31, w = tid >> 5;

    const float4* base4 = xv + (size_t)(h * 32 + w * 8) * 256;

    float4 acc[8];
    #pragma unroll
    for (int j = 0; j < 8; j++) acc[j] = make_float4(0.f, 0.f, 0.f, 0.f);

    #define ISSUE(n, st) do {                                                       \
        unsigned _d = (unsigned)__cvta_generic_to_shared(&s_buf[(st)][w][lane]);    \
        const float4* _s = base4 + (size_t)(n) * 256 + lane;                        \
        _Pragma("unroll")                                                           \
        for (int j = 0; j < 8; j++)                                                 \
            asm volatile("cp.async.cg.shared.global [%0], [%1], 16;"                \
                         :: "r"(_d + j * 512), "l"(_s + j * 32));                   \
        asm volatile("cp.async.commit_group;");                                     \
    } while (0)

    ISSUE(0, 0); ISSUE(1, 1); ISSUE(2, 2);

    #pragma unroll 1
    for (int n = 0; n < 8; n++) {
        asm volatile("cp.async.wait_group 2;" ::: "memory");
        int st = n % 3;

        float4 v[8];
        #pragma unroll
        for (int j = 0; j < 8; j++) v[j] = s_buf[st][w][j * 32 + lane];

        if (n + STAGES < 8) { ISSUE(n + STAGES, st); }
        else { asm volatile("cp.async.commit_group;"); }

        float ss = 0.f;
        #pragma unroll
        for (int j = 0; j < 8; j++)
            ss += v[j].x * v[j].x + v[j].y * v[j].y + v[j].z * v[j].z + v[j].w * v[j].w;
        #pragma unroll
        for (int o = 16; o; o >>= 1) ss += __shfl_xor_sync(0xffffffffu, ss, o);

        float inv = 1.0f / fmaxf(sqrtf(ss), 1e-12f);
        #pragma unroll
        for (int j = 0; j < 8; j++) {
            acc[j].x += v[j].x * inv;
            acc[j].y += v[j].y * inv;
            acc[j].z += v[j].z * inv;
            acc[j].w += v[j].w * inv;
        }
    }
    #undef ISSUE

    #pragma unroll
    for (int j = 0; j < 8; j++) s_buf[0][w][j * 32 + lane] = acc[j];
    __syncthreads();

    #pragma unroll
    for (int i = tid; i < 256; i += 128) {
        float4 r = s_buf[0][0][i];
        #pragma unroll
        for (int w2 = 1; w2 < 4; w2++) {
            float4 u = s_buf[0][w2][i];
            r.x += u.x; r.y += u.y; r.z += u.z; r.w += u.w;
        }
        ((float4*)&g_means[h][t][c][0])[i] = r;  // SUM; /64 folded into gram scale
    }
}

// ================= kernel B: gram -> barrier -> listmle -> final mean =======
// 512 blocks x 128 threads, all co-resident (4/SM max by placement; smem 35KB,
// regs capped by launch_bounds(128,4) -> internal grid barrier is safe).
__device__ __forceinline__ void grid_barrier_b() {
    __syncthreads();
    if (threadIdx.x == 0) {
        __threadfence();
        atomicAdd(&g_bar1, 1);
        while (*((volatile int*)&g_bar1) < GRIDB) __nanosleep(64);
    }
    __syncthreads();
}

__global__ void __launch_bounds__(128, 4) tail_kernel(float* __restrict__ out) {
    __shared__ float As[64][68];   // transposed: As[k][row]
    __shared__ float Bs[64][68];
    __shared__ float s_red[4];
    __shared__ int   s_last;

    int tid = threadIdx.x, lane = tid & 31, w = tid >> 5;

    // ---------- phase gram: 512 blocks = tensor(2) x tile(16) x ks(16) ------
    {
        int b    = blockIdx.x;
        int ks   = b & 15;
        int it   = b >> 4;          // 0..31
        int t    = it >> 4;
        int tile = it & 15;
        int i0 = (tile >> 2) * 64, j0 = (tile & 3) * 64;
        const float* A0 = &g_means[0][t][0][0];
        const float* A1 = &g_means[1][t][0][0];

        int tx = tid & 15, ty = tid >> 4;   // 16 cols-groups x 8 row-groups
        float acc[8][4];
        #pragma unroll
        for (int u = 0; u < 8; u++)
            #pragma unroll
            for (int v = 0; v < 4; v++) acc[u][v] = 0.f;

        int kk = ks * 64;
        // fill both tiles (transposed, halves summed in fixed order)
        #pragma unroll
        for (int l = 0; l < 8; l++) {
            int idx = tid + l * 128;
            int r = idx >> 4, f4 = idx & 15;
            size_t oi = (size_t)(i0 + r) * 1024 + kk + f4 * 4;
            size_t oj = (size_t)(j0 + r) * 1024 + kk + f4 * 4;
            float4 a0 = *(const float4*)&A0[oi];
            float4 a1 = *(const float4*)&A1[oi];
            As[f4 * 4 + 0][r] = a0.x + a1.x;
            As[f4 * 4 + 1][r] = a0.y + a1.y;
            As[f4 * 4 + 2][r] = a0.z + a1.z;
            As[f4 * 4 + 3][r] = a0.w + a1.w;
            float4 b0 = *(const float4*)&A0[oj];
            float4 b1 = *(const float4*)&A1[oj];
            Bs[f4 * 4 + 0][r] = b0.x + b1.x;
            Bs[f4 * 4 + 1][r] = b0.y + b1.y;
            Bs[f4 * 4 + 2][r] = b0.z + b1.z;
            Bs[f4 * 4 + 3][r] = b0.w + b1.w;
        }
        __syncthreads();

        // 8x4 micro-tile, plain scalar FFMA (32 FFMA + 3 LDS.128 per k)
        #pragma unroll 4
        for (int k = 0; k < 64; k++) {
            float4 a0 = *(const float4*)&As[k][ty * 8];
            float4 a1 = *(const float4*)&As[k][ty * 8 + 4];
            float4 bb = *(const float4*)&Bs[k][tx * 4];
            acc[0][0] += a0.x * bb.x; acc[0][1] += a0.x * bb.y; acc[0][2] += a0.x * bb.z; acc[0][3] += a0.x * bb.w;
            acc[1][0] += a0.y * bb.x; acc[1][1] += a0.y * bb.y; acc[1][2] += a0.y * bb.z; acc[1][3] += a0.y * bb.w;
            acc[2][0] += a0.z * bb.x; acc[2][1] += a0.z * bb.y; acc[2][2] += a0.z * bb.z; acc[2][3] += a0.z * bb.w;
            acc[3][0] += a0.w * bb.x; acc[3][1] += a0.w * bb.y; acc[3][2] += a0.w * bb.z; acc[3][3] += a0.w * bb.w;
            acc[4][0] += a1.x * bb.x; acc[4][1] += a1.x * bb.y; acc[4][2] += a1.x * bb.z; acc[4][3] += a1.x * bb.w;
            acc[5][0] += a1.y * bb.x; acc[5][1] += a1.y * bb.y; acc[5][2] += a1.y * bb.z; acc[5][3] += a1.y * bb.w;
            acc[6][0] += a1.z * bb.x; acc[6][1] += a1.z * bb.y; acc[6][2] += a1.z * bb.z; acc[6][3] += a1.z * bb.w;
            acc[7][0] += a1.w * bb.x; acc[7][1] += a1.w * bb.y; acc[7][2] += a1.w * bb.z; acc[7][3] += a1.w * bb.w;
        }

        const float scale = 1.0f / 4096.0f;   // (1/64)^2 from the two means
        #pragma unroll
        for (int u = 0; u < 8; u++) {
            float4 o4 = make_float4(acc[u][0] * scale, acc[u][1] * scale,
                                    acc[u][2] * scale, acc[u][3] * scale);
            *(float4*)&g_gram[ks][t][i0 + ty * 8 + u][j0 + tx * 4] = o4;
        }
    }

    grid_barrier_b();

    // ---------- phase listmle: blocks 0..255, one row each ------------------
    if (blockIdx.x < 256) {
        int i = blockIdx.x;
        float* tr = &As[0][0];            // reuse smem (256 floats)
        float* ps = &Bs[0][0];            // reuse smem (256 floats)

        float p0 = 0.f, t0 = 0.f, p1 = 0.f, t1 = 0.f;
        #pragma unroll
        for (int ks = 0; ks < CK; ks++) {
            p0 += g_gram[ks][0][i][tid];
            p1 += g_gram[ks][0][i][tid + 128];
            t0 += g_gram[ks][1][i][tid];
            t1 += g_gram[ks][1][i][tid + 128];
        }
        tr[tid] = t0; tr[tid + 128] = t1;
        __syncthreads();

        // stable descending rank (ties keep ascending index = argsort(-true))
        int r0 = 0, r1 = 0;
        #pragma unroll 8
        for (int k = 0; k < 256; k++) {
            float tk = tr[k];
            r0 += (tk > t0) || (tk == t0 && k < tid);
            r1 += (tk > t1) || (tk == t1 && k < tid + 128);
        }
        ps[r0] = p0;
        ps[r1] = p1;
        __syncthreads();

        // thread owns sorted positions (2*tid, 2*tid+1)
        float e0 = ps[2 * tid], e1 = ps[2 * tid + 1];
        float x0 = __expf(e0), x1 = __expf(e1);
        float s = x0 + x1;

        #pragma unroll
        for (int off = 1; off < 32; off <<= 1) {
            float v = __shfl_down_sync(0xffffffffu, s, off);
            if (lane + off < 32) s += v;
        }
        if (lane == 0) s_red[w] = s;
        __syncthreads();
        float tail = 0.f;
        #pragma unroll
        for (int w2 = 0; w2 < 4; w2++) if (w2 > w) tail += s_red[w2];
        float S = s + tail;                 // suffix sum at position 2*tid

        float term = (__logf(S + 1e-10f) - e0)
                   + (__logf(S - x0 + 1e-10f) - e1);
        __syncthreads();
        #pragma unroll
        for (int o = 16; o; o >>= 1) term += __shfl_xor_sync(0xffffffffu, term, o);
        if (lane == 0) s_red[w] = term;
        __syncthreads();
        if (tid == 0) {
            g_rowloss[i] = s_red[0] + s_red[1] + s_red[2] + s_red[3];
            __threadfence();
            int v = atomicAdd(&g_done, 1);
            s_last = (v == 255);
        }
        __syncthreads();

        if (s_last) {
            volatile float* rl = g_rowloss;
            float v = rl[tid] + rl[tid + 128];
            #pragma unroll
            for (int o = 16; o; o >>= 1) v += __shfl_xor_sync(0xffffffffu, v, o);
            if (lane == 0) s_red[w] = v;
            __syncthreads();
            if (tid == 0) {
                out[0] = (s_red[0] + s_red[1] + s_red[2] + s_red[3]) * (1.0f / 256.0f);
                g_done = 0;   // reset counters for next graph replay
                g_bar1 = 0;
            }
        }
    }
}

// ---------------- launch ----------------
extern "C" void kernel_launch(void* const* d_in, const int* in_sizes, int n_in,
                              void* d_out, int out_size) {
    const float* emb  = (const float*)d_in[0];
    const float* feat = (const float*)d_in[1];
    float* out = (float*)d_out;

    means_kernel<<<1024, 128>>>(emb, feat);
    tail_kernel<<<GRIDB, 128>>>(out);
}